// round 1
// baseline (speedup 1.0000x reference)
#include <cuda_runtime.h>
#include <math.h>

// Problem constants
#define BB 16
#define NN 1024
#define CC 768
#define HH 12
#define HD 64
#define RR 16
#define MTOT (BB*NN)          // 16384
#define C3 (3*CC)             // 2304
#define SCALE 0.125f          // HD^-0.5

// ---------------- device scratch (no runtime allocation allowed) ----------------
__device__ float g_Wqkv_eff[C3 * CC];     // 2304x768
__device__ float g_Wo_eff[CC * CC];       // 768x768
__device__ float g_bo_eff[CC];
__device__ float g_T[RR * CC];            // A_o @ W_proj
__device__ float g_t2[RR];                // A_o @ b_proj
__device__ float g_qkv[(size_t)MTOT * C3];// 16384x2304
__device__ float g_ctx[(size_t)MTOT * CC];// 16384x768

// ---------------- prologue kernels: fold LoRA into dense weights ----------------
__global__ void build_wqkv(const float* __restrict__ W_qkv,
                           const float* __restrict__ Aq, const float* __restrict__ Bq,
                           const float* __restrict__ Ak, const float* __restrict__ Bk,
                           const float* __restrict__ Av, const float* __restrict__ Bv) {
    int idx = blockIdx.x * blockDim.x + threadIdx.x;
    if (idx >= C3 * CC) return;
    int row = idx / CC;   // 0..2303
    int c   = idx % CC;
    int s = row / CC;     // 0=q,1=k,2=v
    int i = row % CC;
    const float* A; const float* Bt;
    if (s == 0)      { A = Aq; Bt = Bq; }
    else if (s == 1) { A = Ak; Bt = Bk; }
    else             { A = Av; Bt = Bv; }
    float acc = W_qkv[idx];
#pragma unroll
    for (int r = 0; r < RR; r++) acc += Bt[i * RR + r] * A[r * CC + c];
    g_Wqkv_eff[idx] = acc;
}

__global__ void build_T(const float* __restrict__ Ao,
                        const float* __restrict__ Wp,
                        const float* __restrict__ bp) {
    int idx = blockIdx.x * blockDim.x + threadIdx.x;
    if (idx >= RR * CC) return;
    int r = idx / CC, c = idx % CC;
    float acc = 0.f;
    for (int j = 0; j < CC; j++) acc += Ao[r * CC + j] * Wp[j * CC + c];
    g_T[idx] = acc;
    if (c == 0) {
        float a2 = 0.f;
        for (int j = 0; j < CC; j++) a2 += Ao[r * CC + j] * bp[j];
        g_t2[r] = a2;
    }
}

__global__ void build_wo(const float* __restrict__ Wp,
                         const float* __restrict__ Bo,
                         const float* __restrict__ bp) {
    int idx = blockIdx.x * blockDim.x + threadIdx.x;
    if (idx >= CC * CC) return;
    int i = idx / CC, c = idx % CC;
    float acc = Wp[idx];
#pragma unroll
    for (int r = 0; r < RR; r++) acc += Bo[i * RR + r] * g_T[r * CC + c];
    g_Wo_eff[idx] = acc;
    if (c == 0) {
        float b = bp[i];
#pragma unroll
        for (int r = 0; r < RR; r++) b += Bo[i * RR + r] * g_t2[r];
        g_bo_eff[i] = b;
    }
}

// ---------------- GEMM: out[m,n] = sum_k A[m,k]*W[n,k] + bias[n] ----------------
// 128x128 tile, BK=16, 256 threads, 8x8 micro-tile.
__global__ __launch_bounds__(256) void gemm_xWT(
    const float* __restrict__ A, const float* __restrict__ W,
    const float* __restrict__ bias, float* __restrict__ out,
    int M, int Nd, int K)
{
    __shared__ float As[16][128];
    __shared__ float Ws[16][128];
    int bm = blockIdx.y * 128;
    int bn = blockIdx.x * 128;
    int tid = threadIdx.x;
    int ty = tid / 16, tx = tid % 16;

    float acc[8][8];
#pragma unroll
    for (int i = 0; i < 8; i++)
#pragma unroll
        for (int j = 0; j < 8; j++) acc[i][j] = 0.f;

    for (int k0 = 0; k0 < K; k0 += 16) {
#pragma unroll
        for (int l = 0; l < 2; l++) {
            int lid = tid * 2 + l;        // 0..511
            int row = lid >> 2;           // 0..127
            int kc  = (lid & 3) << 2;     // 0,4,8,12
            float4 a = *reinterpret_cast<const float4*>(&A[(size_t)(bm + row) * K + k0 + kc]);
            As[kc + 0][row] = a.x; As[kc + 1][row] = a.y;
            As[kc + 2][row] = a.z; As[kc + 3][row] = a.w;
            float4 w = *reinterpret_cast<const float4*>(&W[(size_t)(bn + row) * K + k0 + kc]);
            Ws[kc + 0][row] = w.x; Ws[kc + 1][row] = w.y;
            Ws[kc + 2][row] = w.z; Ws[kc + 3][row] = w.w;
        }
        __syncthreads();
#pragma unroll
        for (int kk = 0; kk < 16; kk++) {
            float af[8], wf[8];
            *(float4*)&af[0] = *(float4*)&As[kk][ty * 8];
            *(float4*)&af[4] = *(float4*)&As[kk][ty * 8 + 4];
            *(float4*)&wf[0] = *(float4*)&Ws[kk][tx * 8];
            *(float4*)&wf[4] = *(float4*)&Ws[kk][tx * 8 + 4];
#pragma unroll
            for (int i = 0; i < 8; i++)
#pragma unroll
                for (int j = 0; j < 8; j++) acc[i][j] += af[i] * wf[j];
        }
        __syncthreads();
    }

#pragma unroll
    for (int i = 0; i < 8; i++) {
        int m = bm + ty * 8 + i;
#pragma unroll
        for (int j = 0; j < 8; j += 4) {
            int n = bn + tx * 8 + j;
            float4 o;
            o.x = acc[i][j + 0] + bias[n + 0];
            o.y = acc[i][j + 1] + bias[n + 1];
            o.z = acc[i][j + 2] + bias[n + 2];
            o.w = acc[i][j + 3] + bias[n + 3];
            *reinterpret_cast<float4*>(&out[(size_t)m * Nd + n]) = o;
        }
    }
}

// ---------------- flash attention (fp32) ----------------
// Grid: (8 q-tiles, 192 bh). Block: 256 threads.
// Q tile 128 rows, key tile 128, HD=64. Dynamic smem ~170KB.
#define QST(d,q) sQ[(d)*132 + (q)]
#define KST(d,k) sK[(d)*132 + (k)]
#define VSM(k,d) sV[(k)*68 + (d)]
#define PSM(q,k) sP[(q)*132 + (k)]

__global__ __launch_bounds__(256) void flash_attn(const float* __restrict__ qkv,
                                                  float* __restrict__ ctx)
{
    extern __shared__ float smem[];
    float* sQ = smem;                    // 64 x 132
    float* sK = sQ + 64 * 132;           // 64 x 132
    float* sV = sK + 64 * 132;           // 128 x 68
    float* sP = sV + 128 * 68;           // 128 x 132

    int qt = blockIdx.x;                 // 0..7
    int bh = blockIdx.y;                 // 0..191
    int b = bh / HH, h = bh % HH;
    int q0 = qt * 128;
    int tid = threadIdx.x;
    int ty = tid / 16, tx = tid % 16;

    // load Q tile transposed: sQ[d][q]
    const float* qbase = qkv + ((size_t)(b * NN + q0)) * C3 + h * HD;
#pragma unroll
    for (int l = 0; l < 8; l++) {
        int idx = l * 256 + tid;         // 0..2047
        int row = idx >> 4;              // 0..127
        int dc  = (idx & 15) << 2;       // 0..60
        float4 qv = *reinterpret_cast<const float4*>(qbase + (size_t)row * C3 + dc);
        QST(dc + 0, row) = qv.x; QST(dc + 1, row) = qv.y;
        QST(dc + 2, row) = qv.z; QST(dc + 3, row) = qv.w;
    }

    float m_i[8], l_i[8], Oacc[8][4];
#pragma unroll
    for (int i = 0; i < 8; i++) {
        m_i[i] = -1e30f; l_i[i] = 0.f;
#pragma unroll
        for (int j = 0; j < 4; j++) Oacc[i][j] = 0.f;
    }

    for (int kt = 0; kt < NN; kt += 128) {
        // load K (transposed) and V (natural) tiles
        const float* kb = qkv + ((size_t)(b * NN + kt)) * C3 + CC + h * HD;
        const float* vb = qkv + ((size_t)(b * NN + kt)) * C3 + 2 * CC + h * HD;
#pragma unroll
        for (int l = 0; l < 8; l++) {
            int idx = l * 256 + tid;
            int row = idx >> 4;
            int dc  = (idx & 15) << 2;
            float4 kv4 = *reinterpret_cast<const float4*>(kb + (size_t)row * C3 + dc);
            KST(dc + 0, row) = kv4.x; KST(dc + 1, row) = kv4.y;
            KST(dc + 2, row) = kv4.z; KST(dc + 3, row) = kv4.w;
            float4 vv = *reinterpret_cast<const float4*>(vb + (size_t)row * C3 + dc);
            *reinterpret_cast<float4*>(&VSM(row, dc)) = vv;
        }
        __syncthreads();

        // S = Q @ K^T : rows ty*8+i, cols tx*8+j
        float s[8][8];
#pragma unroll
        for (int i = 0; i < 8; i++)
#pragma unroll
            for (int j = 0; j < 8; j++) s[i][j] = 0.f;

#pragma unroll 4
        for (int d = 0; d < 64; d++) {
            float af[8], bf[8];
            *(float4*)&af[0] = *(float4*)&QST(d, ty * 8);
            *(float4*)&af[4] = *(float4*)&QST(d, ty * 8 + 4);
            *(float4*)&bf[0] = *(float4*)&KST(d, tx * 8);
            *(float4*)&bf[4] = *(float4*)&KST(d, tx * 8 + 4);
#pragma unroll
            for (int i = 0; i < 8; i++)
#pragma unroll
                for (int j = 0; j < 8; j++) s[i][j] += af[i] * bf[j];
        }

        // online softmax; row spread across 16 tx lanes (within half-warp)
#pragma unroll
        for (int i = 0; i < 8; i++) {
            float rowmax = -1e30f;
#pragma unroll
            for (int j = 0; j < 8; j++) {
                s[i][j] *= SCALE;
                rowmax = fmaxf(rowmax, s[i][j]);
            }
#pragma unroll
            for (int off = 8; off >= 1; off >>= 1)
                rowmax = fmaxf(rowmax, __shfl_xor_sync(0xffffffffu, rowmax, off));
            float mnew = fmaxf(m_i[i], rowmax);
            float alpha = __expf(m_i[i] - mnew);
            float rsum = 0.f;
            float p[8];
#pragma unroll
            for (int j = 0; j < 8; j++) {
                p[j] = __expf(s[i][j] - mnew);
                rsum += p[j];
            }
#pragma unroll
            for (int off = 8; off >= 1; off >>= 1)
                rsum += __shfl_xor_sync(0xffffffffu, rsum, off);
            l_i[i] = l_i[i] * alpha + rsum;
            m_i[i] = mnew;
#pragma unroll
            for (int j = 0; j < 4; j++) Oacc[i][j] *= alpha;
            float4 p0 = make_float4(p[0], p[1], p[2], p[3]);
            float4 p1 = make_float4(p[4], p[5], p[6], p[7]);
            *reinterpret_cast<float4*>(&PSM(ty * 8 + i, tx * 8)) = p0;
            *reinterpret_cast<float4*>(&PSM(ty * 8 + i, tx * 8 + 4)) = p1;
        }
        __syncthreads();

        // O += P @ V : rows ty*8+i, dims tx*4..tx*4+3
#pragma unroll 2
        for (int k = 0; k < 128; k += 4) {
            float4 pk[8];
#pragma unroll
            for (int i = 0; i < 8; i++)
                pk[i] = *reinterpret_cast<float4*>(&PSM(ty * 8 + i, k));
#pragma unroll
            for (int t = 0; t < 4; t++) {
                float4 v = *reinterpret_cast<float4*>(&VSM(k + t, tx * 4));
#pragma unroll
                for (int i = 0; i < 8; i++) {
                    float pv = (t == 0) ? pk[i].x : (t == 1) ? pk[i].y : (t == 2) ? pk[i].z : pk[i].w;
                    Oacc[i][0] += pv * v.x;
                    Oacc[i][1] += pv * v.y;
                    Oacc[i][2] += pv * v.z;
                    Oacc[i][3] += pv * v.w;
                }
            }
        }
        __syncthreads();
    }

    // write ctx[b, q, h*64 + d]
#pragma unroll
    for (int i = 0; i < 8; i++) {
        float inv = 1.f / l_i[i];
        float4 o;
        o.x = Oacc[i][0] * inv; o.y = Oacc[i][1] * inv;
        o.z = Oacc[i][2] * inv; o.w = Oacc[i][3] * inv;
        size_t m = (size_t)(b * NN + q0 + ty * 8 + i);
        *reinterpret_cast<float4*>(&ctx[m * CC + h * HD + tx * 4]) = o;
    }
}

// ---------------- launch ----------------
extern "C" void kernel_launch(void* const* d_in, const int* in_sizes, int n_in,
                              void* d_out, int out_size) {
    const float* x      = (const float*)d_in[0];
    const float* W_qkv  = (const float*)d_in[1];
    const float* b_qkv  = (const float*)d_in[2];
    const float* W_proj = (const float*)d_in[3];
    const float* b_proj = (const float*)d_in[4];
    const float* A_q = (const float*)d_in[5];  const float* B_q = (const float*)d_in[6];
    const float* A_k = (const float*)d_in[7];  const float* B_k = (const float*)d_in[8];
    const float* A_v = (const float*)d_in[9];  const float* B_v = (const float*)d_in[10];
    const float* A_o = (const float*)d_in[11]; const float* B_o = (const float*)d_in[12];
    float* out = (float*)d_out;

    float *p_Wqkv, *p_Wo, *p_bo, *p_qkv, *p_ctx;
    cudaGetSymbolAddress((void**)&p_Wqkv, g_Wqkv_eff);
    cudaGetSymbolAddress((void**)&p_Wo,   g_Wo_eff);
    cudaGetSymbolAddress((void**)&p_bo,   g_bo_eff);
    cudaGetSymbolAddress((void**)&p_qkv,  g_qkv);
    cudaGetSymbolAddress((void**)&p_ctx,  g_ctx);

    // fold LoRA into weights
    build_wqkv<<<(C3 * CC + 255) / 256, 256>>>(W_qkv, A_q, B_q, A_k, B_k, A_v, B_v);
    build_T<<<(RR * CC + 255) / 256, 256>>>(A_o, W_proj, b_proj);
    build_wo<<<(CC * CC + 255) / 256, 256>>>(W_proj, B_o, b_proj);

    // GEMM1: qkv = x @ W_eff^T + b
    gemm_xWT<<<dim3(C3 / 128, MTOT / 128), 256>>>(x, p_Wqkv, b_qkv, p_qkv, MTOT, C3, CC);

    // flash attention
    int smem_bytes = (64 * 132 + 64 * 132 + 128 * 68 + 128 * 132) * (int)sizeof(float);
    cudaFuncSetAttribute(flash_attn, cudaFuncAttributeMaxDynamicSharedMemorySize, smem_bytes);
    flash_attn<<<dim3(NN / 128, BB * HH), 256, smem_bytes>>>(p_qkv, p_ctx);

    // GEMM2: out = ctx @ Wo_eff^T + b_eff
    gemm_xWT<<<dim3(CC / 128, MTOT / 128), 256>>>(p_ctx, p_Wo, p_bo, out, MTOT, CC, CC);
}

// round 3
// speedup vs baseline: 2.4218x; 2.4218x over previous
#include <cuda_runtime.h>
#include <math.h>
#include <stdint.h>

// Problem constants
#define BB 16
#define NN 1024
#define CC 768
#define HH 12
#define HD 64
#define RR 16
#define MTOT (BB*NN)          // 16384
#define C3 (3*CC)             // 2304
#define SCALE 0.125f          // HD^-0.5

// ---------------- helpers ----------------
__device__ __forceinline__ float tf32r(float x) {
    uint32_t u;
    asm("cvt.rna.tf32.f32 %0, %1;" : "=r"(u) : "f"(x));
    return __uint_as_float(u);
}
__device__ __forceinline__ uint32_t smem_to_u32(const void* p) {
    uint32_t a;
    asm("{ .reg .u64 t; cvta.to.shared.u64 t, %1; cvt.u32.u64 %0, t; }" : "=r"(a) : "l"(p));
    return a;
}

// m16n8k8 tf32 MMA: D += A*B, fp32 accumulate. a[4],b0,b1 are tf32 bit patterns.
#define MMA_TF32(d, a, b0, b1) \
    asm volatile("mma.sync.aligned.m16n8k8.row.col.f32.tf32.tf32.f32 " \
        "{%0,%1,%2,%3}, {%4,%5,%6,%7}, {%8,%9}, {%0,%1,%2,%3};" \
        : "+f"((d)[0]), "+f"((d)[1]), "+f"((d)[2]), "+f"((d)[3]) \
        : "r"((a)[0]), "r"((a)[1]), "r"((a)[2]), "r"((a)[3]), "r"(b0), "r"(b1))

#define CP_ASYNC16(smem_u32, gptr) \
    asm volatile("cp.async.cg.shared.global [%0], [%1], 16;" :: "r"(smem_u32), "l"(gptr))
#define CP_COMMIT() asm volatile("cp.async.commit_group;" ::: "memory")

// ---------------- device scratch ----------------
__device__ float g_Wqkv_eff[C3 * CC];
__device__ float g_Wo_eff[CC * CC];
__device__ float g_bo_eff[CC];
__device__ float g_T[RR * CC];
__device__ float g_t2[RR];
__device__ float g_xr[(size_t)MTOT * CC];    // x rounded to tf32
__device__ float g_qkv[(size_t)MTOT * C3];   // tf32-rounded GEMM1 output
__device__ float g_ctx[(size_t)MTOT * CC];   // tf32-rounded attention output

// ---------------- prologue kernels ----------------
__global__ void round_x(const float* __restrict__ x) {
    int idx = blockIdx.x * blockDim.x + threadIdx.x;
    if (idx < MTOT * CC) g_xr[idx] = tf32r(x[idx]);
}

__global__ void build_wqkv(const float* __restrict__ W_qkv,
                           const float* __restrict__ Aq, const float* __restrict__ Bq,
                           const float* __restrict__ Ak, const float* __restrict__ Bk,
                           const float* __restrict__ Av, const float* __restrict__ Bv) {
    int idx = blockIdx.x * blockDim.x + threadIdx.x;
    if (idx >= C3 * CC) return;
    int row = idx / CC;
    int c   = idx % CC;
    int s = row / CC;
    int i = row % CC;
    const float* A; const float* Bt;
    if (s == 0)      { A = Aq; Bt = Bq; }
    else if (s == 1) { A = Ak; Bt = Bk; }
    else             { A = Av; Bt = Bv; }
    float acc = W_qkv[idx];
#pragma unroll
    for (int r = 0; r < RR; r++) acc += Bt[i * RR + r] * A[r * CC + c];
    g_Wqkv_eff[idx] = tf32r(acc);
}

__global__ void build_T(const float* __restrict__ Ao,
                        const float* __restrict__ Wp,
                        const float* __restrict__ bp) {
    int idx = blockIdx.x * blockDim.x + threadIdx.x;
    if (idx >= RR * CC) return;
    int r = idx / CC, c = idx % CC;
    float acc = 0.f;
    for (int j = 0; j < CC; j++) acc += Ao[r * CC + j] * Wp[j * CC + c];
    g_T[idx] = acc;
    if (c == 0) {
        float a2 = 0.f;
        for (int j = 0; j < CC; j++) a2 += Ao[r * CC + j] * bp[j];
        g_t2[r] = a2;
    }
}

__global__ void build_wo(const float* __restrict__ Wp,
                         const float* __restrict__ Bo,
                         const float* __restrict__ bp) {
    int idx = blockIdx.x * blockDim.x + threadIdx.x;
    if (idx >= CC * CC) return;
    int i = idx / CC, c = idx % CC;
    float acc = Wp[idx];
#pragma unroll
    for (int r = 0; r < RR; r++) acc += Bo[i * RR + r] * g_T[r * CC + c];
    g_Wo_eff[idx] = tf32r(acc);
    if (c == 0) {
        float b = bp[i];
#pragma unroll
        for (int r = 0; r < RR; r++) b += Bo[i * RR + r] * g_t2[r];
        g_bo_eff[i] = b;
    }
}

// ================= tf32 mma.sync GEMM =================
// out[m,n] = sum_k A[m,k]*W[n,k] + bias[n]
// CTA: 128x128 tile, BK=32, double-buffered cp.async.
// 8 warps: 2(M) x 4(N); warp tile 64x32; m16n8k8 frags: 4 m-frags x 4 n-frags.
// smem: A[2][128][36], B[2][128][36]  (stride 36 floats -> conflict-free frag LDS)
#define GM_LDA 36
#define GM_BUF (128 * GM_LDA * 4)         // 18432 bytes per tile buffer
#define GM_SMEM (4 * GM_BUF)              // 73728

template<int DO_ROUND>
__global__ __launch_bounds__(256) void gemm_mma(
    const float* __restrict__ Aop, const float* __restrict__ Wop,
    const float* __restrict__ bias, float* __restrict__ out,
    int Nd, int K)
{
    extern __shared__ float sm[];
    const int tid = threadIdx.x;
    const int wid = tid >> 5;
    const int lane = tid & 31;
    const int g = lane >> 2, tig = lane & 3;
    const int wm = wid >> 2;          // 0..1
    const int wn = wid & 3;           // 0..3
    const int bm = blockIdx.y * 128;
    const int bn = blockIdx.x * 128;
    const uint32_t sb = smem_to_u32(sm);

    const int TOT = K / 32;           // 24

    auto load_stage = [&](int buf, int k0) {
        const float* Ag = Aop + (size_t)bm * K + k0;
        const float* Wg = Wop + (size_t)bn * K + k0;
        uint32_t aB = sb + (uint32_t)buf * GM_BUF;
        uint32_t bB = sb + 2u * GM_BUF + (uint32_t)buf * GM_BUF;
#pragma unroll
        for (int i = 0; i < 4; i++) {
            int idx = tid + i * 256;          // 0..1023
            int row = idx >> 3;
            int c = (idx & 7) << 2;           // float offset 0..28
            CP_ASYNC16(aB + (uint32_t)(row * GM_LDA + c) * 4u, Ag + (size_t)row * K + c);
            CP_ASYNC16(bB + (uint32_t)(row * GM_LDA + c) * 4u, Wg + (size_t)row * K + c);
        }
        CP_COMMIT();
    };

    float acc[4][4][4];
#pragma unroll
    for (int mf = 0; mf < 4; mf++)
#pragma unroll
        for (int nf = 0; nf < 4; nf++)
#pragma unroll
            for (int r = 0; r < 4; r++) acc[mf][nf][r] = 0.f;

    load_stage(0, 0);
    int buf = 0;
    for (int t = 0; t < TOT; t++) {
        if (t + 1 < TOT) {
            load_stage(buf ^ 1, (t + 1) * 32);
            asm volatile("cp.async.wait_group 1;" ::: "memory");
        } else {
            asm volatile("cp.async.wait_group 0;" ::: "memory");
        }
        __syncthreads();

        const float* sA = sm + buf * (GM_BUF / 4);
        const float* sB = sm + 2 * (GM_BUF / 4) + buf * (GM_BUF / 4);
        const uint32_t* uA = (const uint32_t*)sA;
        const uint32_t* uB = (const uint32_t*)sB;

#pragma unroll
        for (int ks = 0; ks < 4; ks++) {
            uint32_t af[4][4];
#pragma unroll
            for (int mf = 0; mf < 4; mf++) {
                int row = wm * 64 + mf * 16 + g;
                int base = row * GM_LDA + ks * 8 + tig;
                af[mf][0] = uA[base];
                af[mf][1] = uA[base + 8 * GM_LDA];
                af[mf][2] = uA[base + 4];
                af[mf][3] = uA[base + 8 * GM_LDA + 4];
            }
            uint32_t bf[4][2];
#pragma unroll
            for (int nf = 0; nf < 4; nf++) {
                int rowb = wn * 32 + nf * 8 + g;
                int baseb = rowb * GM_LDA + ks * 8 + tig;
                bf[nf][0] = uB[baseb];
                bf[nf][1] = uB[baseb + 4];
            }
#pragma unroll
            for (int mf = 0; mf < 4; mf++)
#pragma unroll
                for (int nf = 0; nf < 4; nf++)
                    MMA_TF32(acc[mf][nf], af[mf], bf[nf][0], bf[nf][1]);
        }
        __syncthreads();
        buf ^= 1;
    }

    // epilogue
#pragma unroll
    for (int mf = 0; mf < 4; mf++) {
        int row0 = bm + wm * 64 + mf * 16 + g;
#pragma unroll
        for (int nf = 0; nf < 4; nf++) {
            int col = bn + wn * 32 + nf * 8 + tig * 2;
            float2 bv = *reinterpret_cast<const float2*>(&bias[col]);
            float o0 = acc[mf][nf][0] + bv.x;
            float o1 = acc[mf][nf][1] + bv.y;
            float o2 = acc[mf][nf][2] + bv.x;
            float o3 = acc[mf][nf][3] + bv.y;
            if (DO_ROUND) { o0 = tf32r(o0); o1 = tf32r(o1); o2 = tf32r(o2); o3 = tf32r(o3); }
            *reinterpret_cast<float2*>(&out[(size_t)row0 * Nd + col]) = make_float2(o0, o1);
            *reinterpret_cast<float2*>(&out[(size_t)(row0 + 8) * Nd + col]) = make_float2(o2, o3);
        }
    }
}

// ================= flash attention, tf32 mma.sync =================
// Grid (8 q-tiles, 192 bh), 256 threads / 8 warps.
// Warp w owns q rows w*16 .. w*16+15. Key tiles of 128.
// smem: sQ[128][68], sK[128][68], sV[128][68], sP[128][132]
#define FA_LQ 68
#define FA_LP 132
#define FA_SQ_OFF 0
#define FA_SK_OFF (128 * FA_LQ)
#define FA_SV_OFF (2 * 128 * FA_LQ)
#define FA_SP_OFF (3 * 128 * FA_LQ)
#define FA_SMEM ((3 * 128 * FA_LQ + 128 * FA_LP) * 4)   // 172032 bytes

__global__ __launch_bounds__(256) void flash_attn_tc(const float* __restrict__ qkv,
                                                     float* __restrict__ ctx)
{
    extern __shared__ float sm[];
    float* sQ = sm + FA_SQ_OFF;
    float* sK = sm + FA_SK_OFF;
    float* sV = sm + FA_SV_OFF;
    float* sP = sm + FA_SP_OFF;
    const uint32_t* uQ = (const uint32_t*)sQ;
    const uint32_t* uK = (const uint32_t*)sK;
    const uint32_t* uV = (const uint32_t*)sV;
    const uint32_t* uP = (const uint32_t*)sP;

    const int qt = blockIdx.x;
    const int bh = blockIdx.y;
    const int b = bh / HH, h = bh % HH;
    const int q0 = qt * 128;
    const int tid = threadIdx.x;
    const int wid = tid >> 5;
    const int lane = tid & 31;
    const int g = lane >> 2, tig = lane & 3;
    const int qrow = wid * 16 + g;     // warp-local q row (and +8)

    // ---- load Q tile [128 x 64] ----
    const float* qbase = qkv + ((size_t)(b * NN + q0)) * C3 + h * HD;
#pragma unroll
    for (int l = 0; l < 8; l++) {
        int idx = l * 256 + tid;
        int row = idx >> 4;
        int dc  = (idx & 15) << 2;
        float4 qv = *reinterpret_cast<const float4*>(qbase + (size_t)row * C3 + dc);
        *reinterpret_cast<float4*>(&sQ[row * FA_LQ + dc]) = qv;
    }
    __syncthreads();

    // preload Q fragments for all 8 k-steps (d = ks*8 + ...)
    uint32_t qf[8][4];
#pragma unroll
    for (int ks = 0; ks < 8; ks++) {
        int base = qrow * FA_LQ + ks * 8 + tig;
        qf[ks][0] = uQ[base];
        qf[ks][1] = uQ[base + 8 * FA_LQ];
        qf[ks][2] = uQ[base + 4];
        qf[ks][3] = uQ[base + 8 * FA_LQ + 4];
    }

    float m0 = -1e30f, m1 = -1e30f, l0 = 0.f, l1 = 0.f;
    float oacc[8][4];
#pragma unroll
    for (int nf = 0; nf < 8; nf++)
#pragma unroll
        for (int r = 0; r < 4; r++) oacc[nf][r] = 0.f;

    for (int kt = 0; kt < NN / 128; kt++) {
        __syncthreads();   // protect sK/sV reuse across iterations
        const float* kb = qkv + ((size_t)(b * NN + kt * 128)) * C3 + CC + h * HD;
        const float* vb = qkv + ((size_t)(b * NN + kt * 128)) * C3 + 2 * CC + h * HD;
#pragma unroll
        for (int l = 0; l < 8; l++) {
            int idx = l * 256 + tid;
            int row = idx >> 4;
            int dc  = (idx & 15) << 2;
            float4 kv4 = *reinterpret_cast<const float4*>(kb + (size_t)row * C3 + dc);
            *reinterpret_cast<float4*>(&sK[row * FA_LQ + dc]) = kv4;
            float4 vv = *reinterpret_cast<const float4*>(vb + (size_t)row * C3 + dc);
            *reinterpret_cast<float4*>(&sV[row * FA_LQ + dc]) = vv;
        }
        __syncthreads();

        // ---- S = Q @ K^T   (16 n-frags of 8 keys) ----
        float sacc[16][4];
#pragma unroll
        for (int nf = 0; nf < 16; nf++)
#pragma unroll
            for (int r = 0; r < 4; r++) sacc[nf][r] = 0.f;

#pragma unroll
        for (int ks = 0; ks < 8; ks++) {
#pragma unroll
            for (int nf = 0; nf < 16; nf++) {
                int rowb = (nf * 8 + g) * FA_LQ + ks * 8 + tig;
                uint32_t b0 = uK[rowb];
                uint32_t b1 = uK[rowb + 4];
                MMA_TF32(sacc[nf], qf[ks], b0, b1);
            }
        }

        // ---- online softmax (rows qrow and qrow+8) ----
        float mx0 = -1e30f, mx1 = -1e30f;
#pragma unroll
        for (int nf = 0; nf < 16; nf++) {
            mx0 = fmaxf(mx0, fmaxf(sacc[nf][0], sacc[nf][1]));
            mx1 = fmaxf(mx1, fmaxf(sacc[nf][2], sacc[nf][3]));
        }
        mx0 = fmaxf(mx0, __shfl_xor_sync(0xffffffffu, mx0, 1));
        mx0 = fmaxf(mx0, __shfl_xor_sync(0xffffffffu, mx0, 2));
        mx1 = fmaxf(mx1, __shfl_xor_sync(0xffffffffu, mx1, 1));
        mx1 = fmaxf(mx1, __shfl_xor_sync(0xffffffffu, mx1, 2));

        float mnew0 = fmaxf(m0, mx0 * SCALE);
        float mnew1 = fmaxf(m1, mx1 * SCALE);
        float alpha0 = __expf(m0 - mnew0);
        float alpha1 = __expf(m1 - mnew1);

        float sum0 = 0.f, sum1 = 0.f;
#pragma unroll
        for (int nf = 0; nf < 16; nf++) {
            float p0 = __expf(sacc[nf][0] * SCALE - mnew0);
            float p1 = __expf(sacc[nf][1] * SCALE - mnew0);
            float p2 = __expf(sacc[nf][2] * SCALE - mnew1);
            float p3 = __expf(sacc[nf][3] * SCALE - mnew1);
            sum0 += p0 + p1;
            sum1 += p2 + p3;
            int col = nf * 8 + tig * 2;
            *reinterpret_cast<float2*>(&sP[qrow * FA_LP + col]) =
                make_float2(tf32r(p0), tf32r(p1));
            *reinterpret_cast<float2*>(&sP[(qrow + 8) * FA_LP + col]) =
                make_float2(tf32r(p2), tf32r(p3));
        }
        sum0 += __shfl_xor_sync(0xffffffffu, sum0, 1);
        sum0 += __shfl_xor_sync(0xffffffffu, sum0, 2);
        sum1 += __shfl_xor_sync(0xffffffffu, sum1, 1);
        sum1 += __shfl_xor_sync(0xffffffffu, sum1, 2);

        l0 = l0 * alpha0 + sum0;  m0 = mnew0;
        l1 = l1 * alpha1 + sum1;  m1 = mnew1;

#pragma unroll
        for (int nf = 0; nf < 8; nf++) {
            oacc[nf][0] *= alpha0; oacc[nf][1] *= alpha0;
            oacc[nf][2] *= alpha1; oacc[nf][3] *= alpha1;
        }
        __syncwarp();

        // ---- O += P @ V   (K = 128 keys, 16 k-steps; 8 n-frags of d) ----
#pragma unroll
        for (int kk = 0; kk < 16; kk++) {
            uint32_t pa[4];
            int pbase = qrow * FA_LP + kk * 8 + tig;
            pa[0] = uP[pbase];
            pa[1] = uP[pbase + 8 * FA_LP];
            pa[2] = uP[pbase + 4];
            pa[3] = uP[pbase + 8 * FA_LP + 4];
#pragma unroll
            for (int nf = 0; nf < 8; nf++) {
                int vb0 = (kk * 8 + tig) * FA_LQ + nf * 8 + g;
                uint32_t b0 = uV[vb0];
                uint32_t b1 = uV[vb0 + 4 * FA_LQ];
                MMA_TF32(oacc[nf], pa, b0, b1);
            }
        }
        __syncwarp();
    }

    // ---- epilogue: ctx[b, q, h*64 + d] = O / l  (tf32-rounded for GEMM2) ----
    float inv0 = 1.f / l0, inv1 = 1.f / l1;
    size_t mrow0 = (size_t)(b * NN + q0 + qrow);
#pragma unroll
    for (int nf = 0; nf < 8; nf++) {
        int col = h * HD + nf * 8 + tig * 2;
        *reinterpret_cast<float2*>(&ctx[mrow0 * CC + col]) =
            make_float2(tf32r(oacc[nf][0] * inv0), tf32r(oacc[nf][1] * inv0));
        *reinterpret_cast<float2*>(&ctx[(mrow0 + 8) * CC + col]) =
            make_float2(tf32r(oacc[nf][2] * inv1), tf32r(oacc[nf][3] * inv1));
    }
}

// ---------------- launch ----------------
extern "C" void kernel_launch(void* const* d_in, const int* in_sizes, int n_in,
                              void* d_out, int out_size) {
    const float* x      = (const float*)d_in[0];
    const float* W_qkv  = (const float*)d_in[1];
    const float* b_qkv  = (const float*)d_in[2];
    const float* W_proj = (const float*)d_in[3];
    const float* b_proj = (const float*)d_in[4];
    const float* A_q = (const float*)d_in[5];  const float* B_q = (const float*)d_in[6];
    const float* A_k = (const float*)d_in[7];  const float* B_k = (const float*)d_in[8];
    const float* A_v = (const float*)d_in[9];  const float* B_v = (const float*)d_in[10];
    const float* A_o = (const float*)d_in[11]; const float* B_o = (const float*)d_in[12];
    float* out = (float*)d_out;

    float *p_Wqkv, *p_Wo, *p_bo, *p_qkv, *p_ctx, *p_xr;
    cudaGetSymbolAddress((void**)&p_Wqkv, g_Wqkv_eff);
    cudaGetSymbolAddress((void**)&p_Wo,   g_Wo_eff);
    cudaGetSymbolAddress((void**)&p_bo,   g_bo_eff);
    cudaGetSymbolAddress((void**)&p_qkv,  g_qkv);
    cudaGetSymbolAddress((void**)&p_ctx,  g_ctx);
    cudaGetSymbolAddress((void**)&p_xr,   g_xr);

    // prologue: fold LoRA into dense weights; tf32-round all MMA operands
    round_x<<<(MTOT * CC + 255) / 256, 256>>>(x);
    build_wqkv<<<(C3 * CC + 255) / 256, 256>>>(W_qkv, A_q, B_q, A_k, B_k, A_v, B_v);
    build_T<<<(RR * CC + 255) / 256, 256>>>(A_o, W_proj, b_proj);
    build_wo<<<(CC * CC + 255) / 256, 256>>>(W_proj, B_o, b_proj);

    cudaFuncSetAttribute(gemm_mma<1>, cudaFuncAttributeMaxDynamicSharedMemorySize, GM_SMEM);
    cudaFuncSetAttribute(gemm_mma<0>, cudaFuncAttributeMaxDynamicSharedMemorySize, GM_SMEM);
    cudaFuncSetAttribute(flash_attn_tc, cudaFuncAttributeMaxDynamicSharedMemorySize, FA_SMEM);

    // GEMM1: qkv = xr @ Wqkv_eff^T + b_qkv  (rounded output -> attention operands)
    gemm_mma<1><<<dim3(C3 / 128, MTOT / 128), 256, GM_SMEM>>>(p_xr, p_Wqkv, b_qkv, p_qkv, C3, CC);

    // flash attention (tf32 tensor cores, fp32 softmax)
    flash_attn_tc<<<dim3(NN / 128, BB * HH), 256, FA_SMEM>>>(p_qkv, p_ctx);

    // GEMM2: out = ctx @ Wo_eff^T + bo_eff  (full fp32 output)
    gemm_mma<0><<<dim3(CC / 128, MTOT / 128), 256, GM_SMEM>>>(p_ctx, p_Wo, p_bo, out, CC, CC);
}

// round 4
// speedup vs baseline: 3.0836x; 1.2733x over previous
#include <cuda_runtime.h>
#include <math.h>
#include <stdint.h>

// Problem constants
#define BB 16
#define NN 1024
#define CC 768
#define HH 12
#define HD 64
#define RR 16
#define MTOT (BB*NN)          // 16384
#define C3 (3*CC)             // 2304
#define SCALE 0.125f          // HD^-0.5

// ---------------- helpers ----------------
__device__ __forceinline__ float tf32r(float x) {
    uint32_t u;
    asm("cvt.rna.tf32.f32 %0, %1;" : "=r"(u) : "f"(x));
    return __uint_as_float(u);
}
__device__ __forceinline__ uint32_t smem_to_u32(const void* p) {
    uint32_t a;
    asm("{ .reg .u64 t; cvta.to.shared.u64 t, %1; cvt.u32.u64 %0, t; }" : "=r"(a) : "l"(p));
    return a;
}

// m16n8k8 tf32 MMA: D += A*B, fp32 accumulate.
#define MMA_TF32(d, a, b0, b1) \
    asm volatile("mma.sync.aligned.m16n8k8.row.col.f32.tf32.tf32.f32 " \
        "{%0,%1,%2,%3}, {%4,%5,%6,%7}, {%8,%9}, {%0,%1,%2,%3};" \
        : "+f"((d)[0]), "+f"((d)[1]), "+f"((d)[2]), "+f"((d)[3]) \
        : "r"((a)[0]), "r"((a)[1]), "r"((a)[2]), "r"((a)[3]), "r"(b0), "r"(b1))

#define CP_ASYNC16(smem_u32, gptr) \
    asm volatile("cp.async.cg.shared.global [%0], [%1], 16;" :: "r"(smem_u32), "l"(gptr))
#define CP_COMMIT() asm volatile("cp.async.commit_group;" ::: "memory")

// ---------------- device scratch ----------------
__device__ float g_Wqkv_eff[C3 * CC];
__device__ float g_Wo_eff[CC * CC];
__device__ float g_bo_eff[CC];
__device__ float g_T[RR * CC];
__device__ float g_t2[RR];
__device__ float g_xr[(size_t)MTOT * CC];    // x rounded to tf32
__device__ float g_qkv[(size_t)MTOT * C3];   // tf32-rounded GEMM1 output
__device__ float g_ctx[(size_t)MTOT * CC];   // tf32-rounded attention output

// ---------------- prologue kernels ----------------
__global__ void round_x(const float* __restrict__ x) {
    int idx = blockIdx.x * blockDim.x + threadIdx.x;
    if (idx < MTOT * CC) g_xr[idx] = tf32r(x[idx]);
}

__global__ void build_wqkv(const float* __restrict__ W_qkv,
                           const float* __restrict__ Aq, const float* __restrict__ Bq,
                           const float* __restrict__ Ak, const float* __restrict__ Bk,
                           const float* __restrict__ Av, const float* __restrict__ Bv) {
    int idx = blockIdx.x * blockDim.x + threadIdx.x;
    if (idx >= C3 * CC) return;
    int row = idx / CC;
    int c   = idx % CC;
    int s = row / CC;
    int i = row % CC;
    const float* A; const float* Bt;
    if (s == 0)      { A = Aq; Bt = Bq; }
    else if (s == 1) { A = Ak; Bt = Bk; }
    else             { A = Av; Bt = Bv; }
    float acc = W_qkv[idx];
#pragma unroll
    for (int r = 0; r < RR; r++) acc += Bt[i * RR + r] * A[r * CC + c];
    g_Wqkv_eff[idx] = tf32r(acc);
}

__global__ void build_T(const float* __restrict__ Ao,
                        const float* __restrict__ Wp,
                        const float* __restrict__ bp) {
    int idx = blockIdx.x * blockDim.x + threadIdx.x;
    if (idx >= RR * CC) return;
    int r = idx / CC, c = idx % CC;
    float acc = 0.f;
    for (int j = 0; j < CC; j++) acc += Ao[r * CC + j] * Wp[j * CC + c];
    g_T[idx] = acc;
    if (c == 0) {
        float a2 = 0.f;
        for (int j = 0; j < CC; j++) a2 += Ao[r * CC + j] * bp[j];
        g_t2[r] = a2;
    }
}

__global__ void build_wo(const float* __restrict__ Wp,
                         const float* __restrict__ Bo,
                         const float* __restrict__ bp) {
    int idx = blockIdx.x * blockDim.x + threadIdx.x;
    if (idx >= CC * CC) return;
    int i = idx / CC, c = idx % CC;
    float acc = Wp[idx];
#pragma unroll
    for (int r = 0; r < RR; r++) acc += Bo[i * RR + r] * g_T[r * CC + c];
    g_Wo_eff[idx] = tf32r(acc);
    if (c == 0) {
        float b = bp[i];
#pragma unroll
        for (int r = 0; r < RR; r++) b += Bo[i * RR + r] * g_t2[r];
        g_bo_eff[i] = b;
    }
}

// ================= tf32 mma.sync GEMM, 128x256 tile =================
// out[m,n] = sum_k A[m,k]*W[n,k] + bias[n]
// BK=32, 3-stage cp.async pipeline. 8 warps 2(M)x4(N), warp tile 64x64.
#define GM_LD 36
#define GM_ABUF (128 * GM_LD)               // floats per A stage
#define GM_BBUF (256 * GM_LD)               // floats per B stage
#define GM_NST 3
#define GM_SMEM (GM_NST * (GM_ABUF + GM_BBUF) * 4)   // 165888 B

template<int DO_ROUND>
__global__ __launch_bounds__(256, 1) void gemm_mma(
    const float* __restrict__ Aop, const float* __restrict__ Wop,
    const float* __restrict__ bias, float* __restrict__ out,
    int Nd, int K)
{
    extern __shared__ float sm[];
    const uint32_t* usm = (const uint32_t*)sm;
    const int tid = threadIdx.x;
    const int wid = tid >> 5;
    const int lane = tid & 31;
    const int g = lane >> 2, tig = lane & 3;
    const int wm = wid >> 2;          // 0..1
    const int wn = wid & 3;           // 0..3
    const int bm = blockIdx.y * 128;
    const int bn = blockIdx.x * 256;
    const uint32_t sb = smem_to_u32(sm);
    const int TOT = K / 32;           // 24

    auto load_stage = [&](int st, int k0) {
        const float* Ag = Aop + (size_t)bm * K + k0;
        const float* Wg = Wop + (size_t)bn * K + k0;
        uint32_t aB = sb + (uint32_t)st * (GM_ABUF + GM_BBUF) * 4u;
        uint32_t bB = aB + GM_ABUF * 4u;
#pragma unroll
        for (int i = 0; i < 4; i++) {
            int idx = tid + i * 256;          // 0..1023
            int row = idx >> 3;
            int c = (idx & 7) << 2;
            CP_ASYNC16(aB + (uint32_t)(row * GM_LD + c) * 4u, Ag + (size_t)row * K + c);
        }
#pragma unroll
        for (int i = 0; i < 8; i++) {
            int idx = tid + i * 256;          // 0..2047
            int row = idx >> 3;
            int c = (idx & 7) << 2;
            CP_ASYNC16(bB + (uint32_t)(row * GM_LD + c) * 4u, Wg + (size_t)row * K + c);
        }
        CP_COMMIT();
    };

    float acc[4][8][4];
#pragma unroll
    for (int mf = 0; mf < 4; mf++)
#pragma unroll
        for (int nf = 0; nf < 8; nf++)
#pragma unroll
            for (int r = 0; r < 4; r++) acc[mf][nf][r] = 0.f;

    load_stage(0, 0);
    load_stage(1, 32);

    for (int t = 0; t < TOT; t++) {
        if (t + 1 < TOT) asm volatile("cp.async.wait_group 1;" ::: "memory");
        else             asm volatile("cp.async.wait_group 0;" ::: "memory");
        __syncthreads();
        if (t + 2 < TOT) load_stage((t + 2) % GM_NST, (t + 2) * 32);

        const int st = t % GM_NST;
        const uint32_t aOff = (uint32_t)st * (GM_ABUF + GM_BBUF);
        const uint32_t bOff = aOff + GM_ABUF;

#pragma unroll
        for (int ks = 0; ks < 4; ks++) {
            uint32_t af[4][4];
#pragma unroll
            for (int mf = 0; mf < 4; mf++) {
                int row = wm * 64 + mf * 16 + g;
                uint32_t base = aOff + row * GM_LD + ks * 8 + tig;
                af[mf][0] = usm[base];
                af[mf][1] = usm[base + 8 * GM_LD];
                af[mf][2] = usm[base + 4];
                af[mf][3] = usm[base + 8 * GM_LD + 4];
            }
            uint32_t bf[8][2];
#pragma unroll
            for (int nf = 0; nf < 8; nf++) {
                int rowb = wn * 64 + nf * 8 + g;
                uint32_t baseb = bOff + rowb * GM_LD + ks * 8 + tig;
                bf[nf][0] = usm[baseb];
                bf[nf][1] = usm[baseb + 4];
            }
#pragma unroll
            for (int mf = 0; mf < 4; mf++)
#pragma unroll
                for (int nf = 0; nf < 8; nf++)
                    MMA_TF32(acc[mf][nf], af[mf], bf[nf][0], bf[nf][1]);
        }
    }

    // epilogue
#pragma unroll
    for (int mf = 0; mf < 4; mf++) {
        int row0 = bm + wm * 64 + mf * 16 + g;
#pragma unroll
        for (int nf = 0; nf < 8; nf++) {
            int col = bn + wn * 64 + nf * 8 + tig * 2;
            float2 bv = *reinterpret_cast<const float2*>(&bias[col]);
            float o0 = acc[mf][nf][0] + bv.x;
            float o1 = acc[mf][nf][1] + bv.y;
            float o2 = acc[mf][nf][2] + bv.x;
            float o3 = acc[mf][nf][3] + bv.y;
            if (DO_ROUND) { o0 = tf32r(o0); o1 = tf32r(o1); o2 = tf32r(o2); o3 = tf32r(o3); }
            *reinterpret_cast<float2*>(&out[(size_t)row0 * Nd + col]) = make_float2(o0, o1);
            *reinterpret_cast<float2*>(&out[(size_t)(row0 + 8) * Nd + col]) = make_float2(o2, o3);
        }
    }
}

// ================= flash attention, tf32 mma.sync, cp.async, P-in-regs =================
// Grid (8 q-tiles, 192 bh), 256 threads / 8 warps. Warp w: q rows w*16..w*16+15.
// smem: sQ[128][68], sK[2][128][68], sV[2][128][72]   (178 KB)
#define FA_LK 68
#define FA_LV 72
#define FA_QOFF 0
#define FA_KOFF (128 * FA_LK)                // 8704
#define FA_VOFF (FA_KOFF + 2 * 128 * FA_LK)  // 26112
#define FA_KBUF (128 * FA_LK)
#define FA_VBUF (128 * FA_LV)
#define FA_SMEM ((FA_VOFF + 2 * FA_VBUF) * 4)   // 178176 B

__global__ __launch_bounds__(256, 1) void flash_attn_tc(const float* __restrict__ qkv,
                                                        float* __restrict__ ctx)
{
    extern __shared__ float sm[];
    const uint32_t* usm = (const uint32_t*)sm;
    const uint32_t sb = smem_to_u32(sm);

    const int qt = blockIdx.x;
    const int bh = blockIdx.y;
    const int b = bh / HH, h = bh % HH;
    const int q0 = qt * 128;
    const int tid = threadIdx.x;
    const int wid = tid >> 5;
    const int lane = tid & 31;
    const int g = lane >> 2, tig = lane & 3;
    const int qrow = wid * 16 + g;

    // issue cp.async K/V loads for a key tile into buffer `bufi`
    auto load_kv = [&](int kt, int bufi) {
        const float* kb = qkv + ((size_t)(b * NN + kt * 128)) * C3 + CC + h * HD;
        const float* vb = qkv + ((size_t)(b * NN + kt * 128)) * C3 + 2 * CC + h * HD;
        uint32_t kB = sb + (FA_KOFF + bufi * FA_KBUF) * 4u;
        uint32_t vB = sb + (FA_VOFF + bufi * FA_VBUF) * 4u;
#pragma unroll
        for (int l = 0; l < 8; l++) {
            int idx = l * 256 + tid;
            int row = idx >> 4;
            int dc  = (idx & 15) << 2;
            CP_ASYNC16(kB + (uint32_t)(row * FA_LK + dc) * 4u, kb + (size_t)row * C3 + dc);
            CP_ASYNC16(vB + (uint32_t)(row * FA_LV + dc) * 4u, vb + (size_t)row * C3 + dc);
        }
        CP_COMMIT();
    };

    load_kv(0, 0);

    // Q tile [128 x 64] via plain loads
    const float* qbase = qkv + ((size_t)(b * NN + q0)) * C3 + h * HD;
#pragma unroll
    for (int l = 0; l < 8; l++) {
        int idx = l * 256 + tid;
        int row = idx >> 4;
        int dc  = (idx & 15) << 2;
        float4 qv = *reinterpret_cast<const float4*>(qbase + (size_t)row * C3 + dc);
        *reinterpret_cast<float4*>(&sm[FA_QOFF + row * FA_LK + dc]) = qv;
    }

    uint32_t qf[8][4];
    float m0 = -1e30f, m1 = -1e30f, l0 = 0.f, l1 = 0.f;
    float oacc[8][4];
#pragma unroll
    for (int nf = 0; nf < 8; nf++)
#pragma unroll
        for (int r = 0; r < 4; r++) oacc[nf][r] = 0.f;

    int buf = 0;
    for (int kt = 0; kt < NN / 128; kt++) {
        asm volatile("cp.async.wait_group 0;" ::: "memory");
        __syncthreads();
        if (kt == 0) {
            // preload Q fragments (all 8 k-steps)
#pragma unroll
            for (int ks = 0; ks < 8; ks++) {
                uint32_t base = FA_QOFF + qrow * FA_LK + ks * 8 + tig;
                qf[ks][0] = usm[base];
                qf[ks][1] = usm[base + 8 * FA_LK];
                qf[ks][2] = usm[base + 4];
                qf[ks][3] = usm[base + 8 * FA_LK + 4];
            }
        }
        if (kt + 1 < NN / 128) load_kv(kt + 1, buf ^ 1);

        const uint32_t kOff = FA_KOFF + buf * FA_KBUF;
        const uint32_t vOff = FA_VOFF + buf * FA_VBUF;

        // ---- S = Q @ K^T  (16 n-frags of 8 keys) ----
        float sacc[16][4];
#pragma unroll
        for (int nf = 0; nf < 16; nf++)
#pragma unroll
            for (int r = 0; r < 4; r++) sacc[nf][r] = 0.f;

#pragma unroll
        for (int ks = 0; ks < 8; ks++) {
            uint32_t kb0 = kOff + g * FA_LK + ks * 8 + tig;
#pragma unroll
            for (int nf = 0; nf < 16; nf++) {
                uint32_t addr = kb0 + nf * 8 * FA_LK;
                uint32_t b0 = usm[addr];
                uint32_t b1 = usm[addr + 4];
                MMA_TF32(sacc[nf], qf[ks], b0, b1);
            }
        }

        // ---- online softmax (rows qrow, qrow+8) ----
        float mx0 = -1e30f, mx1 = -1e30f;
#pragma unroll
        for (int nf = 0; nf < 16; nf++) {
            mx0 = fmaxf(mx0, fmaxf(sacc[nf][0], sacc[nf][1]));
            mx1 = fmaxf(mx1, fmaxf(sacc[nf][2], sacc[nf][3]));
        }
        mx0 = fmaxf(mx0, __shfl_xor_sync(0xffffffffu, mx0, 1));
        mx0 = fmaxf(mx0, __shfl_xor_sync(0xffffffffu, mx0, 2));
        mx1 = fmaxf(mx1, __shfl_xor_sync(0xffffffffu, mx1, 1));
        mx1 = fmaxf(mx1, __shfl_xor_sync(0xffffffffu, mx1, 2));

        float mnew0 = fmaxf(m0, mx0 * SCALE);
        float mnew1 = fmaxf(m1, mx1 * SCALE);
        float alpha0 = __expf(m0 - mnew0);
        float alpha1 = __expf(m1 - mnew1);

        float p0a[16], p1a[16], p2a[16], p3a[16];
        float sum0 = 0.f, sum1 = 0.f;
#pragma unroll
        for (int nf = 0; nf < 16; nf++) {
            p0a[nf] = tf32r(__expf(sacc[nf][0] * SCALE - mnew0));
            p1a[nf] = tf32r(__expf(sacc[nf][1] * SCALE - mnew0));
            p2a[nf] = tf32r(__expf(sacc[nf][2] * SCALE - mnew1));
            p3a[nf] = tf32r(__expf(sacc[nf][3] * SCALE - mnew1));
            sum0 += p0a[nf] + p1a[nf];
            sum1 += p2a[nf] + p3a[nf];
        }
        sum0 += __shfl_xor_sync(0xffffffffu, sum0, 1);
        sum0 += __shfl_xor_sync(0xffffffffu, sum0, 2);
        sum1 += __shfl_xor_sync(0xffffffffu, sum1, 1);
        sum1 += __shfl_xor_sync(0xffffffffu, sum1, 2);

        l0 = l0 * alpha0 + sum0;  m0 = mnew0;
        l1 = l1 * alpha1 + sum1;  m1 = mnew1;

#pragma unroll
        for (int nf = 0; nf < 8; nf++) {
            oacc[nf][0] *= alpha0; oacc[nf][1] *= alpha0;
            oacc[nf][2] *= alpha1; oacc[nf][3] *= alpha1;
        }

        // ---- O += P @ V : P D-frags -> A-frags via intra-quad shuffles ----
        const int srcA = (lane & ~3) | (tig >> 1);
        const int srcB = srcA + 2;
        const bool odd = (tig & 1);
#pragma unroll
        for (int kk = 0; kk < 16; kk++) {
            float q00 = __shfl_sync(0xffffffffu, p0a[kk], srcA);
            float q01 = __shfl_sync(0xffffffffu, p1a[kk], srcA);
            float q20 = __shfl_sync(0xffffffffu, p0a[kk], srcB);
            float q21 = __shfl_sync(0xffffffffu, p1a[kk], srcB);
            float q10 = __shfl_sync(0xffffffffu, p2a[kk], srcA);
            float q11 = __shfl_sync(0xffffffffu, p3a[kk], srcA);
            float q30 = __shfl_sync(0xffffffffu, p2a[kk], srcB);
            float q31 = __shfl_sync(0xffffffffu, p3a[kk], srcB);
            uint32_t pa[4];
            pa[0] = __float_as_uint(odd ? q01 : q00);
            pa[1] = __float_as_uint(odd ? q11 : q10);
            pa[2] = __float_as_uint(odd ? q21 : q20);
            pa[3] = __float_as_uint(odd ? q31 : q30);

            uint32_t vb0 = vOff + (kk * 8 + tig) * FA_LV + g;
#pragma unroll
            for (int nf = 0; nf < 8; nf++) {
                uint32_t addr = vb0 + nf * 8;
                uint32_t b0 = usm[addr];
                uint32_t b1 = usm[addr + 4 * FA_LV];
                MMA_TF32(oacc[nf], pa, b0, b1);
            }
        }
        buf ^= 1;
    }

    // ---- epilogue: ctx = O / l  (tf32-rounded, feeds GEMM2) ----
    float inv0 = 1.f / l0, inv1 = 1.f / l1;
    size_t mrow0 = (size_t)(b * NN + q0 + qrow);
#pragma unroll
    for (int nf = 0; nf < 8; nf++) {
        int col = h * HD + nf * 8 + tig * 2;
        *reinterpret_cast<float2*>(&ctx[mrow0 * CC + col]) =
            make_float2(tf32r(oacc[nf][0] * inv0), tf32r(oacc[nf][1] * inv0));
        *reinterpret_cast<float2*>(&ctx[(mrow0 + 8) * CC + col]) =
            make_float2(tf32r(oacc[nf][2] * inv1), tf32r(oacc[nf][3] * inv1));
    }
}

// ---------------- launch ----------------
extern "C" void kernel_launch(void* const* d_in, const int* in_sizes, int n_in,
                              void* d_out, int out_size) {
    const float* x      = (const float*)d_in[0];
    const float* W_qkv  = (const float*)d_in[1];
    const float* b_qkv  = (const float*)d_in[2];
    const float* W_proj = (const float*)d_in[3];
    const float* b_proj = (const float*)d_in[4];
    const float* A_q = (const float*)d_in[5];  const float* B_q = (const float*)d_in[6];
    const float* A_k = (const float*)d_in[7];  const float* B_k = (const float*)d_in[8];
    const float* A_v = (const float*)d_in[9];  const float* B_v = (const float*)d_in[10];
    const float* A_o = (const float*)d_in[11]; const float* B_o = (const float*)d_in[12];
    float* out = (float*)d_out;

    float *p_Wqkv, *p_Wo, *p_bo, *p_qkv, *p_ctx, *p_xr;
    cudaGetSymbolAddress((void**)&p_Wqkv, g_Wqkv_eff);
    cudaGetSymbolAddress((void**)&p_Wo,   g_Wo_eff);
    cudaGetSymbolAddress((void**)&p_bo,   g_bo_eff);
    cudaGetSymbolAddress((void**)&p_qkv,  g_qkv);
    cudaGetSymbolAddress((void**)&p_ctx,  g_ctx);
    cudaGetSymbolAddress((void**)&p_xr,   g_xr);

    // prologue: fold LoRA into dense weights; tf32-round all MMA operands
    round_x<<<(MTOT * CC + 255) / 256, 256>>>(x);
    build_wqkv<<<(C3 * CC + 255) / 256, 256>>>(W_qkv, A_q, B_q, A_k, B_k, A_v, B_v);
    build_T<<<(RR * CC + 255) / 256, 256>>>(A_o, W_proj, b_proj);
    build_wo<<<(CC * CC + 255) / 256, 256>>>(W_proj, B_o, b_proj);

    cudaFuncSetAttribute(gemm_mma<1>, cudaFuncAttributeMaxDynamicSharedMemorySize, GM_SMEM);
    cudaFuncSetAttribute(gemm_mma<0>, cudaFuncAttributeMaxDynamicSharedMemorySize, GM_SMEM);
    cudaFuncSetAttribute(flash_attn_tc, cudaFuncAttributeMaxDynamicSharedMemorySize, FA_SMEM);

    // GEMM1: qkv = xr @ Wqkv_eff^T + b_qkv  (rounded output -> attention operands)
    gemm_mma<1><<<dim3(C3 / 256, MTOT / 128), 256, GM_SMEM>>>(p_xr, p_Wqkv, b_qkv, p_qkv, C3, CC);

    // flash attention (tf32 tensor cores, fp32 softmax)
    flash_attn_tc<<<dim3(NN / 128, BB * HH), 256, FA_SMEM>>>(p_qkv, p_ctx);

    // GEMM2: out = ctx @ Wo_eff^T + bo_eff  (full fp32 output)
    gemm_mma<0><<<dim3(CC / 256, MTOT / 128), 256, GM_SMEM>>>(p_ctx, p_Wo, p_bo, out, CC, CC);
}

// round 6
// speedup vs baseline: 5.0925x; 1.6515x over previous
#include <cuda_runtime.h>
#include <cuda_fp16.h>
#include <math.h>
#include <stdint.h>

// Problem constants
#define BB 16
#define NN 1024
#define CC 768
#define HH 12
#define HD 64
#define RR 16
#define MTOT (BB*NN)          // 16384
#define C3 (3*CC)             // 2304
#define SCALE 0.125f          // HD^-0.5

// ---------------- helpers ----------------
__device__ __forceinline__ uint32_t smem_to_u32(const void* p) {
    uint32_t a;
    asm("{ .reg .u64 t; cvta.to.shared.u64 t, %1; cvt.u32.u64 %0, t; }" : "=r"(a) : "l"(p));
    return a;
}

// m16n8k16 fp16 MMA, fp32 accumulate. a[4], b0, b1 are packed half2 bit patterns.
#define MMA_F16(d, a, b0, b1) \
    asm volatile("mma.sync.aligned.m16n8k16.row.col.f32.f16.f16.f32 " \
        "{%0,%1,%2,%3}, {%4,%5,%6,%7}, {%8,%9}, {%0,%1,%2,%3};" \
        : "+f"((d)[0]), "+f"((d)[1]), "+f"((d)[2]), "+f"((d)[3]) \
        : "r"((a)[0]), "r"((a)[1]), "r"((a)[2]), "r"((a)[3]), "r"(b0), "r"(b1))

#define LDSM_X4_T(r0, r1, r2, r3, addr) \
    asm volatile("ldmatrix.sync.aligned.m8n8.x4.trans.shared.b16 {%0,%1,%2,%3}, [%4];" \
        : "=r"(r0), "=r"(r1), "=r"(r2), "=r"(r3) : "r"(addr))

#define CP_ASYNC16(smem_u32, gptr) \
    asm volatile("cp.async.cg.shared.global [%0], [%1], 16;" :: "r"(smem_u32), "l"(gptr))
#define CP_COMMIT() asm volatile("cp.async.commit_group;" ::: "memory")

__device__ __forceinline__ uint32_t pack_h2(float lo, float hi) {
    __half2 h = __floats2half2_rn(lo, hi);
    return *reinterpret_cast<uint32_t*>(&h);
}

// ---------------- device scratch ----------------
__device__ __half g_x_h[(size_t)MTOT * CC];
__device__ __half g_Wqkv_h[C3 * CC];
__device__ __half g_Wo_h[CC * CC];
__device__ float  g_bo_eff[CC];
__device__ float  g_T[RR * CC];
__device__ float  g_t2[RR];
__device__ __half g_qkv[(size_t)MTOT * C3];
__device__ __half g_ctx[(size_t)MTOT * CC];

// ---------------- prologue kernels ----------------
__global__ void round_x(const float* __restrict__ x) {
    int idx = blockIdx.x * blockDim.x + threadIdx.x;
    if (idx < MTOT * CC) g_x_h[idx] = __float2half_rn(x[idx]);
}

__global__ void build_wqkv(const float* __restrict__ W_qkv,
                           const float* __restrict__ Aq, const float* __restrict__ Bq,
                           const float* __restrict__ Ak, const float* __restrict__ Bk,
                           const float* __restrict__ Av, const float* __restrict__ Bv) {
    int idx = blockIdx.x * blockDim.x + threadIdx.x;
    if (idx >= C3 * CC) return;
    int row = idx / CC;
    int c   = idx % CC;
    int s = row / CC;
    int i = row % CC;
    const float* A; const float* Bt;
    if (s == 0)      { A = Aq; Bt = Bq; }
    else if (s == 1) { A = Ak; Bt = Bk; }
    else             { A = Av; Bt = Bv; }
    float acc = W_qkv[idx];
#pragma unroll
    for (int r = 0; r < RR; r++) acc += Bt[i * RR + r] * A[r * CC + c];
    g_Wqkv_h[idx] = __float2half_rn(acc);
}

__global__ void build_T(const float* __restrict__ Ao,
                        const float* __restrict__ Wp,
                        const float* __restrict__ bp) {
    int idx = blockIdx.x * blockDim.x + threadIdx.x;
    if (idx >= RR * CC) return;
    int r = idx / CC, c = idx % CC;
    float acc = 0.f;
    for (int j = 0; j < CC; j++) acc += Ao[r * CC + j] * Wp[j * CC + c];
    g_T[idx] = acc;
    if (c == 0) {
        float a2 = 0.f;
        for (int j = 0; j < CC; j++) a2 += Ao[r * CC + j] * bp[j];
        g_t2[r] = a2;
    }
}

__global__ void build_wo(const float* __restrict__ Wp,
                         const float* __restrict__ Bo,
                         const float* __restrict__ bp) {
    int idx = blockIdx.x * blockDim.x + threadIdx.x;
    if (idx >= CC * CC) return;
    int i = idx / CC, c = idx % CC;
    float acc = Wp[idx];
#pragma unroll
    for (int r = 0; r < RR; r++) acc += Bo[i * RR + r] * g_T[r * CC + c];
    g_Wo_h[idx] = __float2half_rn(acc);
    if (c == 0) {
        float b = bp[i];
#pragma unroll
        for (int r = 0; r < RR; r++) b += Bo[i * RR + r] * g_t2[r];
        g_bo_eff[i] = b;
    }
}

// ================= fp16 mma.sync GEMM, 128x256 tile =================
// out[m,n] = sum_k A[m,k]*W[n,k] + bias[n];  A,W half [rows][K]
// BK=64 halves, 3-stage cp.async. 8 warps 2(M)x4(N), warp tile 64x64.
// smem rows padded to 72 halves (36 words) -> conflict-free 32b frag loads.
#define GM_LDH 72
#define GM_LDW 36
#define GM_ABYTES (128 * GM_LDH * 2)        // 18432
#define GM_BBYTES (256 * GM_LDH * 2)        // 36864
#define GM_STAGE (GM_ABYTES + GM_BBYTES)    // 55296
#define GM_NST 3
#define GM_SMEM (GM_NST * GM_STAGE)         // 165888

template<typename OT>
__global__ __launch_bounds__(256, 1) void gemm_mma(
    const __half* __restrict__ Aop, const __half* __restrict__ Wop,
    const float* __restrict__ bias, OT* __restrict__ out,
    int Nd, int K)
{
    extern __shared__ char smraw[];
    const uint32_t* usm = (const uint32_t*)smraw;
    const int tid = threadIdx.x;
    const int wid = tid >> 5;
    const int lane = tid & 31;
    const int g = lane >> 2, tig = lane & 3;
    const int wm = wid >> 2;          // 0..1
    const int wn = wid & 3;           // 0..3
    const int bm = blockIdx.y * 128;
    const int bn = blockIdx.x * 256;
    const uint32_t sb = smem_to_u32(smraw);
    const int TOT = K / 64;           // 12

    auto load_stage = [&](int st, int k0) {
        const __half* Ag = Aop + (size_t)bm * K + k0;
        const __half* Wg = Wop + (size_t)bn * K + k0;
        uint32_t aB = sb + (uint32_t)st * GM_STAGE;
        uint32_t bB = aB + GM_ABYTES;
#pragma unroll
        for (int i = 0; i < 4; i++) {
            int idx = tid + i * 256;          // 0..1023
            int row = idx >> 3;
            int c = idx & 7;                  // 8-half chunk
            CP_ASYNC16(aB + (uint32_t)(row * 144 + c * 16), Ag + (size_t)row * K + c * 8);
        }
#pragma unroll
        for (int i = 0; i < 8; i++) {
            int idx = tid + i * 256;          // 0..2047
            int row = idx >> 3;
            int c = idx & 7;
            CP_ASYNC16(bB + (uint32_t)(row * 144 + c * 16), Wg + (size_t)row * K + c * 8);
        }
        CP_COMMIT();
    };

    float acc[4][8][4];
#pragma unroll
    for (int mf = 0; mf < 4; mf++)
#pragma unroll
        for (int nf = 0; nf < 8; nf++)
#pragma unroll
            for (int r = 0; r < 4; r++) acc[mf][nf][r] = 0.f;

    load_stage(0, 0);
    load_stage(1, 64);

    for (int t = 0; t < TOT; t++) {
        if (t + 1 < TOT) asm volatile("cp.async.wait_group 1;" ::: "memory");
        else             asm volatile("cp.async.wait_group 0;" ::: "memory");
        __syncthreads();
        if (t + 2 < TOT) load_stage((t + 2) % GM_NST, (t + 2) * 64);

        const int st = t % GM_NST;
        const uint32_t aW = (uint32_t)st * (GM_STAGE / 4);       // word offset
        const uint32_t bW = aW + GM_ABYTES / 4;

#pragma unroll
        for (int ks = 0; ks < 4; ks++) {     // k16 steps
            uint32_t af[4][4];
#pragma unroll
            for (int mf = 0; mf < 4; mf++) {
                uint32_t base = aW + (uint32_t)((wm * 64 + mf * 16 + g) * GM_LDW + ks * 8 + tig);
                af[mf][0] = usm[base];
                af[mf][1] = usm[base + 8 * GM_LDW];
                af[mf][2] = usm[base + 4];
                af[mf][3] = usm[base + 8 * GM_LDW + 4];
            }
            uint32_t bf[8][2];
#pragma unroll
            for (int nf = 0; nf < 8; nf++) {
                uint32_t baseb = bW + (uint32_t)((wn * 64 + nf * 8 + g) * GM_LDW + ks * 8 + tig);
                bf[nf][0] = usm[baseb];
                bf[nf][1] = usm[baseb + 4];
            }
#pragma unroll
            for (int mf = 0; mf < 4; mf++)
#pragma unroll
                for (int nf = 0; nf < 8; nf++)
                    MMA_F16(acc[mf][nf], af[mf], bf[nf][0], bf[nf][1]);
        }
    }

    // epilogue: D-frag (g,2tig),(g,2tig+1),(g+8,...)
#pragma unroll
    for (int mf = 0; mf < 4; mf++) {
        int row0 = bm + wm * 64 + mf * 16 + g;
#pragma unroll
        for (int nf = 0; nf < 8; nf++) {
            int col = bn + wn * 64 + nf * 8 + tig * 2;
            float2 bv = *reinterpret_cast<const float2*>(&bias[col]);
            float o0 = acc[mf][nf][0] + bv.x;
            float o1 = acc[mf][nf][1] + bv.y;
            float o2 = acc[mf][nf][2] + bv.x;
            float o3 = acc[mf][nf][3] + bv.y;
            if constexpr (sizeof(OT) == 2) {
                __half2 h01 = __floats2half2_rn(o0, o1);
                __half2 h23 = __floats2half2_rn(o2, o3);
                *reinterpret_cast<__half2*>(&out[(size_t)row0 * Nd + col]) = h01;
                *reinterpret_cast<__half2*>(&out[(size_t)(row0 + 8) * Nd + col]) = h23;
            } else {
                *reinterpret_cast<float2*>(&out[(size_t)row0 * Nd + col]) = make_float2(o0, o1);
                *reinterpret_cast<float2*>(&out[(size_t)(row0 + 8) * Nd + col]) = make_float2(o2, o3);
            }
        }
    }
}

// ================= flash attention, fp16 mma.sync =================
// Grid (8 q-tiles, 192 bh), 256 threads / 8 warps; warp w: q rows w*16..+15.
// smem (halves): sQ[128][72], sK[2][128][72], sV[2][128][72]  -> 92160 B, 2 CTAs/SM
#define FA_LDH 72
#define FA_LDW 36
#define FA_TILEB (128 * FA_LDH * 2)          // 18432 B per tile
#define FA_QOFF 0
#define FA_KOFF FA_TILEB                     // 18432
#define FA_VOFF (FA_KOFF + 2 * FA_TILEB)     // 55296
#define FA_SMEM (FA_VOFF + 2 * FA_TILEB)     // 92160 B

__global__ __launch_bounds__(256, 2) void flash_attn_tc(const __half* __restrict__ qkv,
                                                        __half* __restrict__ ctx)
{
    extern __shared__ char smraw[];
    const uint32_t* usm = (const uint32_t*)smraw;
    const uint32_t sb = smem_to_u32(smraw);

    const int qt = blockIdx.x;
    const int bh = blockIdx.y;
    const int b = bh / HH, h = bh % HH;
    const int q0 = qt * 128;
    const int tid = threadIdx.x;
    const int wid = tid >> 5;
    const int lane = tid & 31;
    const int g = lane >> 2, tig = lane & 3;
    const int qrow = wid * 16 + g;

    // ---- issue Q tile cp.async ----
    {
        const __half* qb = qkv + ((size_t)(b * NN + q0)) * C3 + h * HD;
#pragma unroll
        for (int i = 0; i < 4; i++) {
            int idx = tid + i * 256;
            int row = idx >> 3;
            int c = idx & 7;
            CP_ASYNC16(sb + FA_QOFF + (uint32_t)(row * 144 + c * 16), qb + (size_t)row * C3 + c * 8);
        }
        CP_COMMIT();
    }

    auto load_kv = [&](int kt, int bufi) {
        const __half* kb = qkv + ((size_t)(b * NN + kt * 128)) * C3 + CC + h * HD;
        const __half* vb = qkv + ((size_t)(b * NN + kt * 128)) * C3 + 2 * CC + h * HD;
        uint32_t kB = sb + FA_KOFF + (uint32_t)bufi * FA_TILEB;
        uint32_t vB = sb + FA_VOFF + (uint32_t)bufi * FA_TILEB;
#pragma unroll
        for (int i = 0; i < 4; i++) {
            int idx = tid + i * 256;
            int row = idx >> 3;
            int c = idx & 7;
            CP_ASYNC16(kB + (uint32_t)(row * 144 + c * 16), kb + (size_t)row * C3 + c * 8);
            CP_ASYNC16(vB + (uint32_t)(row * 144 + c * 16), vb + (size_t)row * C3 + c * 8);
        }
        CP_COMMIT();
    };

    load_kv(0, 0);

    float m0 = -1e30f, m1 = -1e30f, l0 = 0.f, l1 = 0.f;
    float oacc[8][4];
#pragma unroll
    for (int nf = 0; nf < 8; nf++)
#pragma unroll
        for (int r = 0; r < 4; r++) oacc[nf][r] = 0.f;

    int buf = 0;
    for (int kt = 0; kt < NN / 128; kt++) {
        asm volatile("cp.async.wait_group 0;" ::: "memory");
        __syncthreads();
        if (kt + 1 < NN / 128) load_kv(kt + 1, buf ^ 1);

        const uint32_t kW = (FA_KOFF / 4) + (uint32_t)buf * (FA_TILEB / 4);
        const uint32_t vBase = sb + FA_VOFF + (uint32_t)buf * FA_TILEB;   // BYTE address incl. smem base

        // ---- S = Q @ K^T (fp32 accum), 16 n-frags of 8 keys ----
        float sacc[16][4];
#pragma unroll
        for (int nf = 0; nf < 16; nf++)
#pragma unroll
            for (int r = 0; r < 4; r++) sacc[nf][r] = 0.f;

#pragma unroll
        for (int ks = 0; ks < 4; ks++) {     // k16 over HD=64
            uint32_t qa[4];
            uint32_t qbase = (FA_QOFF / 4) + (uint32_t)(qrow * FA_LDW + ks * 8 + tig);
            qa[0] = usm[qbase];
            qa[1] = usm[qbase + 8 * FA_LDW];
            qa[2] = usm[qbase + 4];
            qa[3] = usm[qbase + 8 * FA_LDW + 4];
#pragma unroll
            for (int nf = 0; nf < 16; nf++) {
                uint32_t kb0 = kW + (uint32_t)((nf * 8 + g) * FA_LDW + ks * 8 + tig);
                uint32_t b0 = usm[kb0];
                uint32_t b1 = usm[kb0 + 4];
                MMA_F16(sacc[nf], qa, b0, b1);
            }
        }

        // ---- online softmax (rows qrow, qrow+8) ----
        float mx0 = -1e30f, mx1 = -1e30f;
#pragma unroll
        for (int nf = 0; nf < 16; nf++) {
            mx0 = fmaxf(mx0, fmaxf(sacc[nf][0], sacc[nf][1]));
            mx1 = fmaxf(mx1, fmaxf(sacc[nf][2], sacc[nf][3]));
        }
        mx0 = fmaxf(mx0, __shfl_xor_sync(0xffffffffu, mx0, 1));
        mx0 = fmaxf(mx0, __shfl_xor_sync(0xffffffffu, mx0, 2));
        mx1 = fmaxf(mx1, __shfl_xor_sync(0xffffffffu, mx1, 1));
        mx1 = fmaxf(mx1, __shfl_xor_sync(0xffffffffu, mx1, 2));

        float mnew0 = fmaxf(m0, mx0 * SCALE);
        float mnew1 = fmaxf(m1, mx1 * SCALE);
        float alpha0 = __expf(m0 - mnew0);
        float alpha1 = __expf(m1 - mnew1);

        float sum0 = 0.f, sum1 = 0.f;
#pragma unroll
        for (int nf = 0; nf < 16; nf++) {
            sacc[nf][0] = __expf(sacc[nf][0] * SCALE - mnew0);
            sacc[nf][1] = __expf(sacc[nf][1] * SCALE - mnew0);
            sacc[nf][2] = __expf(sacc[nf][2] * SCALE - mnew1);
            sacc[nf][3] = __expf(sacc[nf][3] * SCALE - mnew1);
            sum0 += sacc[nf][0] + sacc[nf][1];
            sum1 += sacc[nf][2] + sacc[nf][3];
        }
        sum0 += __shfl_xor_sync(0xffffffffu, sum0, 1);
        sum0 += __shfl_xor_sync(0xffffffffu, sum0, 2);
        sum1 += __shfl_xor_sync(0xffffffffu, sum1, 1);
        sum1 += __shfl_xor_sync(0xffffffffu, sum1, 2);

        l0 = l0 * alpha0 + sum0;  m0 = mnew0;
        l1 = l1 * alpha1 + sum1;  m1 = mnew1;

#pragma unroll
        for (int nf = 0; nf < 8; nf++) {
            oacc[nf][0] *= alpha0; oacc[nf][1] *= alpha0;
            oacc[nf][2] *= alpha1; oacc[nf][3] *= alpha1;
        }

        // ---- O += P @ V ----
        // P a-frags: local fp32->fp16 pack (layouts align). V b-frags: ldmatrix.x4.trans
        const int ldsm_row = (lane & 15);         // k within 16-chunk
        const int ldsm_colh = 8 * (lane >> 4);    // +0 or +8 halves
#pragma unroll
        for (int kk = 0; kk < 8; kk++) {          // k16 chunks over 128 keys
            uint32_t pa[4];
            pa[0] = pack_h2(sacc[2 * kk][0],     sacc[2 * kk][1]);
            pa[1] = pack_h2(sacc[2 * kk][2],     sacc[2 * kk][3]);
            pa[2] = pack_h2(sacc[2 * kk + 1][0], sacc[2 * kk + 1][1]);
            pa[3] = pack_h2(sacc[2 * kk + 1][2], sacc[2 * kk + 1][3]);

            uint32_t vrow = vBase + (uint32_t)((kk * 16 + ldsm_row) * 144 + ldsm_colh * 2);
#pragma unroll
            for (int nf16 = 0; nf16 < 4; nf16++) {   // d blocks of 16
                uint32_t r0, r1, r2, r3;
                LDSM_X4_T(r0, r1, r2, r3, vrow + (uint32_t)(nf16 * 32));
                MMA_F16(oacc[nf16 * 2], pa, r0, r1);
                MMA_F16(oacc[nf16 * 2 + 1], pa, r2, r3);
            }
        }
        buf ^= 1;
    }

    // ---- epilogue: ctx = O / l (fp16, feeds GEMM2) ----
    float inv0 = 1.f / l0, inv1 = 1.f / l1;
    size_t mrow0 = (size_t)(b * NN + q0 + qrow);
#pragma unroll
    for (int nf = 0; nf < 8; nf++) {
        int col = h * HD + nf * 8 + tig * 2;
        __half2 h01 = __floats2half2_rn(oacc[nf][0] * inv0, oacc[nf][1] * inv0);
        __half2 h23 = __floats2half2_rn(oacc[nf][2] * inv1, oacc[nf][3] * inv1);
        *reinterpret_cast<__half2*>(&ctx[mrow0 * CC + col]) = h01;
        *reinterpret_cast<__half2*>(&ctx[(mrow0 + 8) * CC + col]) = h23;
    }
}

// ---------------- launch ----------------
extern "C" void kernel_launch(void* const* d_in, const int* in_sizes, int n_in,
                              void* d_out, int out_size) {
    const float* x      = (const float*)d_in[0];
    const float* W_qkv  = (const float*)d_in[1];
    const float* b_qkv  = (const float*)d_in[2];
    const float* W_proj = (const float*)d_in[3];
    const float* b_proj = (const float*)d_in[4];
    const float* A_q = (const float*)d_in[5];  const float* B_q = (const float*)d_in[6];
    const float* A_k = (const float*)d_in[7];  const float* B_k = (const float*)d_in[8];
    const float* A_v = (const float*)d_in[9];  const float* B_v = (const float*)d_in[10];
    const float* A_o = (const float*)d_in[11]; const float* B_o = (const float*)d_in[12];
    float* out = (float*)d_out;

    __half *p_xh, *p_Wqkv, *p_Wo, *p_qkv, *p_ctx;
    float *p_bo;
    cudaGetSymbolAddress((void**)&p_xh,   g_x_h);
    cudaGetSymbolAddress((void**)&p_Wqkv, g_Wqkv_h);
    cudaGetSymbolAddress((void**)&p_Wo,   g_Wo_h);
    cudaGetSymbolAddress((void**)&p_bo,   g_bo_eff);
    cudaGetSymbolAddress((void**)&p_qkv,  g_qkv);
    cudaGetSymbolAddress((void**)&p_ctx,  g_ctx);

    // prologue: fold LoRA into dense weights; all MMA operands to fp16
    round_x<<<(MTOT * CC + 255) / 256, 256>>>(x);
    build_wqkv<<<(C3 * CC + 255) / 256, 256>>>(W_qkv, A_q, B_q, A_k, B_k, A_v, B_v);
    build_T<<<(RR * CC + 255) / 256, 256>>>(A_o, W_proj, b_proj);
    build_wo<<<(CC * CC + 255) / 256, 256>>>(W_proj, B_o, b_proj);

    cudaFuncSetAttribute(gemm_mma<__half>, cudaFuncAttributeMaxDynamicSharedMemorySize, GM_SMEM);
    cudaFuncSetAttribute(gemm_mma<float>,  cudaFuncAttributeMaxDynamicSharedMemorySize, GM_SMEM);
    cudaFuncSetAttribute(flash_attn_tc,    cudaFuncAttributeMaxDynamicSharedMemorySize, FA_SMEM);

    // GEMM1: qkv = x_h @ Wqkv_h^T + b_qkv  (fp16 out -> attention operands)
    gemm_mma<__half><<<dim3(C3 / 256, MTOT / 128), 256, GM_SMEM>>>(p_xh, p_Wqkv, b_qkv, p_qkv, C3, CC);

    // flash attention (fp16 tensor cores, fp32 softmax/accum)
    flash_attn_tc<<<dim3(NN / 128, BB * HH), 256, FA_SMEM>>>(p_qkv, p_ctx);

    // GEMM2: out = ctx @ Wo_h^T + bo_eff  (fp32 out)
    gemm_mma<float><<<dim3(CC / 256, MTOT / 128), 256, GM_SMEM>>>(p_ctx, p_Wo, p_bo, out, CC, CC);
}